// round 1
// baseline (speedup 1.0000x reference)
#include <cuda_runtime.h>

#define BINS   64
#define NB     (BINS * BINS)
#define BATCH  2
#define NELEM  (192 * 224 * 192)   /* 8,257,536 per batch */
#define N4     (NELEM / 4)
#define EPSF   1e-10f

// Scratch (no allocations allowed in kernel_launch)
__device__ unsigned int g_hist[BATCH * NB];
// layout: [combo*2 + 0] = min-encoding, [combo*2 + 1] = max-encoding
// combo = arr*2 + b,  arr: 0=fixed 1=warped
__device__ unsigned int g_minmax[8];

// Order-preserving float -> uint encoding (monotone under unsigned compare)
__device__ __forceinline__ unsigned int fenc(float f) {
    unsigned int u = __float_as_uint(f);
    return (u & 0x80000000u) ? ~u : (u | 0x80000000u);
}
__device__ __forceinline__ float fdec(unsigned int e) {
    unsigned int u = (e & 0x80000000u) ? (e & 0x7fffffffu) : ~e;
    return __uint_as_float(u);
}

__global__ void initK() {
    int i = blockIdx.x * blockDim.x + threadIdx.x;
    if (i < BATCH * NB) g_hist[i] = 0u;
    if (i < 8) g_minmax[i] = (i & 1) ? 0u : 0xFFFFFFFFu;  // max-slots start at 0, min-slots at UINT_MAX
}

__global__ void minmaxK(const float4* __restrict__ fixedp,
                        const float4* __restrict__ warpedp) {
    int combo = blockIdx.y;            // 0..3
    int arr = combo >> 1, b = combo & 1;
    const float4* src = (arr ? warpedp : fixedp) + (size_t)b * N4;

    float vmin = 3.4e38f, vmax = -3.4e38f;
    for (int i = blockIdx.x * blockDim.x + threadIdx.x; i < N4;
         i += gridDim.x * blockDim.x) {
        float4 v = src[i];
        vmin = fminf(vmin, fminf(fminf(v.x, v.y), fminf(v.z, v.w)));
        vmax = fmaxf(vmax, fmaxf(fmaxf(v.x, v.y), fmaxf(v.z, v.w)));
    }
    #pragma unroll
    for (int o = 16; o; o >>= 1) {
        vmin = fminf(vmin, __shfl_down_sync(0xFFFFFFFFu, vmin, o));
        vmax = fmaxf(vmax, __shfl_down_sync(0xFFFFFFFFu, vmax, o));
    }
    __shared__ float smin[8], smax[8];
    int w = threadIdx.x >> 5, l = threadIdx.x & 31;
    if (l == 0) { smin[w] = vmin; smax[w] = vmax; }
    __syncthreads();
    if (threadIdx.x == 0) {
        float m = smin[0], M = smax[0];
        for (int k = 1; k < (int)(blockDim.x >> 5); k++) {
            m = fminf(m, smin[k]);
            M = fmaxf(M, smax[k]);
        }
        atomicMin(&g_minmax[combo * 2 + 0], fenc(m));
        atomicMax(&g_minmax[combo * 2 + 1], fenc(M));
    }
}

__global__ void histK(const float* __restrict__ fixedp,
                      const float* __restrict__ warpedp) {
    int b = blockIdx.y;
    __shared__ unsigned int sh[NB];
    for (int i = threadIdx.x; i < NB; i += blockDim.x) sh[i] = 0u;
    __syncthreads();

    float fmn = fdec(g_minmax[b * 2 + 0]);
    float fmx = fdec(g_minmax[b * 2 + 1]);
    float wmn = fdec(g_minmax[(2 + b) * 2 + 0]);
    float wmx = fdec(g_minmax[(2 + b) * 2 + 1]);
    float fs = (float)(BINS - 1) / (fmx - fmn + EPSF);
    float ws = (float)(BINS - 1) / (wmx - wmn + EPSF);

    const float4* f4 = (const float4*)(fixedp + (size_t)b * NELEM);
    const float4* w4 = (const float4*)(warpedp + (size_t)b * NELEM);

    for (int i = blockIdx.x * blockDim.x + threadIdx.x; i < N4;
         i += gridDim.x * blockDim.x) {
        float4 f = f4[i];
        float4 w = w4[i];
        int fi, wi;
        fi = min(max((int)((f.x - fmn) * fs), 0), BINS - 1);
        wi = min(max((int)((w.x - wmn) * ws), 0), BINS - 1);
        atomicAdd(&sh[fi * BINS + wi], 1u);
        fi = min(max((int)((f.y - fmn) * fs), 0), BINS - 1);
        wi = min(max((int)((w.y - wmn) * ws), 0), BINS - 1);
        atomicAdd(&sh[fi * BINS + wi], 1u);
        fi = min(max((int)((f.z - fmn) * fs), 0), BINS - 1);
        wi = min(max((int)((w.z - wmn) * ws), 0), BINS - 1);
        atomicAdd(&sh[fi * BINS + wi], 1u);
        fi = min(max((int)((f.w - fmn) * fs), 0), BINS - 1);
        wi = min(max((int)((w.w - wmn) * ws), 0), BINS - 1);
        atomicAdd(&sh[fi * BINS + wi], 1u);
    }
    __syncthreads();

    unsigned int* gh = g_hist + b * NB;
    for (int i = threadIdx.x; i < NB; i += blockDim.x) {
        unsigned int v = sh[i];
        if (v) atomicAdd(&gh[i], v);
    }
}

__global__ void finalK(const float* __restrict__ pred,
                       const float* __restrict__ tru,
                       float* __restrict__ out) {
    __shared__ float red[256];
    __shared__ float pf[BINS], pw[BINS];
    int t = threadIdx.x;
    float nmi_sum = 0.f;

    for (int b = 0; b < BATCH; b++) {
        const unsigned int* h = g_hist + b * NB;

        // total count
        float s = 0.f;
        for (int i = t; i < NB; i += 256) s += (float)h[i];
        red[t] = s; __syncthreads();
        for (int k = 128; k; k >>= 1) { if (t < k) red[t] += red[t + k]; __syncthreads(); }
        float invN = 1.f / (red[0] + EPSF);
        __syncthreads();

        // joint entropy
        float hj = 0.f;
        for (int i = t; i < NB; i += 256) {
            float p = (float)h[i] * invN;
            hj -= p * logf(p + EPSF);
        }
        red[t] = hj; __syncthreads();
        for (int k = 128; k; k >>= 1) { if (t < k) red[t] += red[t + k]; __syncthreads(); }
        float h_j = red[0];
        __syncthreads();

        // marginals
        if (t < BINS) {
            float rs = 0.f, cs = 0.f;
            for (int j = 0; j < BINS; j++) {
                rs += (float)h[t * BINS + j];
                cs += (float)h[j * BINS + t];
            }
            pf[t] = rs * invN;
            pw[t] = cs * invN;
        }
        __syncthreads();

        float hfp = 0.f, hwp = 0.f;
        if (t < BINS) {
            hfp = -pf[t] * logf(pf[t] + EPSF);
            hwp = -pw[t] * logf(pw[t] + EPSF);
        }
        red[t] = hfp; __syncthreads();
        for (int k = 128; k; k >>= 1) { if (t < k) red[t] += red[t + k]; __syncthreads(); }
        float h_f = red[0]; __syncthreads();
        red[t] = hwp; __syncthreads();
        for (int k = 128; k; k >>= 1) { if (t < k) red[t] += red[t + k]; __syncthreads(); }
        float h_w = red[0]; __syncthreads();

        float mi = h_f + h_w - h_j;
        nmi_sum += 2.f * mi / (h_f + h_w + EPSF);
    }

    if (t == 0) {
        float mse = 0.f;
        for (int i = 0; i < BATCH * 12; i++) {
            float d = pred[i] - tru[i];
            mse += d * d;
        }
        mse /= (float)(BATCH * 12);
        out[0] = mse - nmi_sum / (float)BATCH;   // + LAMBDA_SIM * (-mean(nmi))
    }
}

extern "C" void kernel_launch(void* const* d_in, const int* in_sizes, int n_in,
                              void* d_out, int out_size) {
    const float* pred   = (const float*)d_in[0];
    const float* tru    = (const float*)d_in[1];
    const float* fixedp = (const float*)d_in[2];
    const float* warpedp= (const float*)d_in[3];

    initK<<<(BATCH * NB + 255) / 256, 256>>>();

    dim3 g1(256, 4);
    minmaxK<<<g1, 256>>>((const float4*)fixedp, (const float4*)warpedp);

    dim3 g2(296, 2);
    histK<<<g2, 256>>>(fixedp, warpedp);

    finalK<<<1, 256>>>(pred, tru, (float*)d_out);
}

// round 2
// speedup vs baseline: 1.1044x; 1.1044x over previous
#include <cuda_runtime.h>

#define BINS   64
#define NB     (BINS * BINS)
#define BATCH  2
#define NELEM  (192 * 224 * 192)   /* 8,257,536 per batch */
#define N4     (NELEM / 4)
#define EPSF   1e-10f

// Scratch (no allocations allowed). These are SELF-RESTORING: finalK returns
// them to exactly these initial values, so every kernel_launch call sees the
// same state (deterministic across correctness run + graph replays).
__device__ unsigned int g_hist[BATCH * NB];   // static-zeroed; re-zeroed by finalK
// layout: [combo*2+0]=min-enc (init UINT_MAX), [combo*2+1]=max-enc (init 0)
// combo = arr*2 + b, arr: 0=fixed 1=warped
__device__ unsigned int g_minmax[8] = {
    0xFFFFFFFFu, 0u, 0xFFFFFFFFu, 0u,
    0xFFFFFFFFu, 0u, 0xFFFFFFFFu, 0u
};

// Order-preserving float <-> uint encoding (monotone under unsigned compare)
__device__ __forceinline__ unsigned int fenc(float f) {
    unsigned int u = __float_as_uint(f);
    return (u & 0x80000000u) ? ~u : (u | 0x80000000u);
}
__device__ __forceinline__ float fdec(unsigned int e) {
    unsigned int u = (e & 0x80000000u) ? (e & 0x7fffffffu) : ~e;
    return __uint_as_float(u);
}

// One pass over both volumes: per-batch min/max of fixed AND warped.
__global__ void minmaxK(const float4* __restrict__ fixedp,
                        const float4* __restrict__ warpedp) {
    int b = blockIdx.y;
    const float4* f4 = fixedp  + (size_t)b * N4;
    const float4* w4 = warpedp + (size_t)b * N4;

    float fmn = 3.4e38f, fmx = -3.4e38f, wmn = 3.4e38f, wmx = -3.4e38f;
    for (int i = blockIdx.x * blockDim.x + threadIdx.x; i < N4;
         i += gridDim.x * blockDim.x) {
        float4 f = f4[i];
        float4 w = w4[i];
        fmn = fminf(fmn, fminf(fminf(f.x, f.y), fminf(f.z, f.w)));
        fmx = fmaxf(fmx, fmaxf(fmaxf(f.x, f.y), fmaxf(f.z, f.w)));
        wmn = fminf(wmn, fminf(fminf(w.x, w.y), fminf(w.z, w.w)));
        wmx = fmaxf(wmx, fmaxf(fmaxf(w.x, w.y), fmaxf(w.z, w.w)));
    }
    #pragma unroll
    for (int o = 16; o; o >>= 1) {
        fmn = fminf(fmn, __shfl_down_sync(0xFFFFFFFFu, fmn, o));
        fmx = fmaxf(fmx, __shfl_down_sync(0xFFFFFFFFu, fmx, o));
        wmn = fminf(wmn, __shfl_down_sync(0xFFFFFFFFu, wmn, o));
        wmx = fmaxf(wmx, __shfl_down_sync(0xFFFFFFFFu, wmx, o));
    }
    __shared__ float s0[8], s1[8], s2[8], s3[8];
    int w = threadIdx.x >> 5, l = threadIdx.x & 31;
    if (l == 0) { s0[w] = fmn; s1[w] = fmx; s2[w] = wmn; s3[w] = wmx; }
    __syncthreads();
    if (threadIdx.x == 0) {
        int nw = blockDim.x >> 5;
        float a = s0[0], bx = s1[0], c = s2[0], d = s3[0];
        for (int k = 1; k < nw; k++) {
            a = fminf(a, s0[k]); bx = fmaxf(bx, s1[k]);
            c = fminf(c, s2[k]); d = fmaxf(d, s3[k]);
        }
        atomicMin(&g_minmax[(0 * 2 + b) * 2 + 0], fenc(a));
        atomicMax(&g_minmax[(0 * 2 + b) * 2 + 1], fenc(bx));
        atomicMin(&g_minmax[(1 * 2 + b) * 2 + 0], fenc(c));
        atomicMax(&g_minmax[(1 * 2 + b) * 2 + 1], fenc(d));
    }
}

__global__ void histK(const float* __restrict__ fixedp,
                      const float* __restrict__ warpedp) {
    int b = blockIdx.y;
    __shared__ unsigned int sh[NB];
    for (int i = threadIdx.x; i < NB; i += blockDim.x) sh[i] = 0u;
    __syncthreads();

    float fmn = fdec(g_minmax[(0 * 2 + b) * 2 + 0]);
    float fmx = fdec(g_minmax[(0 * 2 + b) * 2 + 1]);
    float wmn = fdec(g_minmax[(1 * 2 + b) * 2 + 0]);
    float wmx = fdec(g_minmax[(1 * 2 + b) * 2 + 1]);
    float fs = (float)(BINS - 1) / (fmx - fmn + EPSF);
    float ws = (float)(BINS - 1) / (wmx - wmn + EPSF);

    const float4* f4 = (const float4*)(fixedp + (size_t)b * NELEM);
    const float4* w4 = (const float4*)(warpedp + (size_t)b * NELEM);

    for (int i = blockIdx.x * blockDim.x + threadIdx.x; i < N4;
         i += gridDim.x * blockDim.x) {
        float4 f = f4[i];
        float4 w = w4[i];
        int fi, wi;
        fi = min(max((int)((f.x - fmn) * fs), 0), BINS - 1);
        wi = min(max((int)((w.x - wmn) * ws), 0), BINS - 1);
        atomicAdd(&sh[fi * BINS + wi], 1u);
        fi = min(max((int)((f.y - fmn) * fs), 0), BINS - 1);
        wi = min(max((int)((w.y - wmn) * ws), 0), BINS - 1);
        atomicAdd(&sh[fi * BINS + wi], 1u);
        fi = min(max((int)((f.z - fmn) * fs), 0), BINS - 1);
        wi = min(max((int)((w.z - wmn) * ws), 0), BINS - 1);
        atomicAdd(&sh[fi * BINS + wi], 1u);
        fi = min(max((int)((f.w - fmn) * fs), 0), BINS - 1);
        wi = min(max((int)((w.w - wmn) * ws), 0), BINS - 1);
        atomicAdd(&sh[fi * BINS + wi], 1u);
    }
    __syncthreads();

    unsigned int* gh = g_hist + b * NB;
    for (int i = threadIdx.x; i < NB; i += blockDim.x) {
        unsigned int v = sh[i];
        if (v) atomicAdd(&gh[i], v);
    }
}

// Single-block epilogue. Note: joint histogram total == NELEM exactly (every
// element is clipped into a bin), so invN is a compile-time constant and no
// sum-reduction pass is needed.
__global__ void finalK(const float* __restrict__ pred,
                       const float* __restrict__ tru,
                       float* __restrict__ out) {
    __shared__ float sh[NB];      // one batch's histogram as float
    __shared__ float red[8];
    __shared__ float hsum[3];     // h_j, h_f, h_w for current batch
    const float invN = 1.0f / ((float)NELEM + EPSF);

    int t = threadIdx.x;          // 256 threads
    int w = t >> 5, l = t & 31;
    float nmi_sum = 0.f;

    for (int b = 0; b < BATCH; b++) {
        unsigned int* gh = g_hist + b * NB;

        // Stage histogram in shared, zero global behind us (self-restore),
        // and accumulate joint entropy in the same sweep.
        float hj = 0.f;
        #pragma unroll
        for (int k = 0; k < NB / 256; k++) {
            int i = t + k * 256;
            float c = (float)gh[i];
            gh[i] = 0u;
            sh[i] = c;
            float p = c * invN;
            hj -= p * __logf(p + EPSF);
        }
        #pragma unroll
        for (int o = 16; o; o >>= 1) hj += __shfl_down_sync(0xFFFFFFFFu, hj, o);
        if (l == 0) red[w] = hj;
        __syncthreads();
        if (t == 0) {
            float s = red[0];
            #pragma unroll
            for (int k = 1; k < 8; k++) s += red[k];
            hsum[0] = s;
        }

        // Marginals in parallel: threads 0-63 rows (p_f), 64-127 cols (p_w)
        float hterm = 0.f;
        if (t < 64) {
            float rs = 0.f;
            #pragma unroll
            for (int j = 0; j < BINS; j++) rs += sh[t * BINS + j];
            float p = rs * invN;
            hterm = -p * __logf(p + EPSF);
        } else if (t < 128) {
            int c = t - 64;
            float cs = 0.f;
            #pragma unroll
            for (int j = 0; j < BINS; j++) cs += sh[j * BINS + c];
            float p = cs * invN;
            hterm = -p * __logf(p + EPSF);
        }
        #pragma unroll
        for (int o = 16; o; o >>= 1)
            hterm += __shfl_down_sync(0xFFFFFFFFu, hterm, o);
        if (l == 0 && w < 4) {
            // warps 0,1 -> h_f halves; warps 2,3 -> h_w halves
            atomicAdd(&hsum[1 + (w >> 1)], hterm);
        }
        // hsum[1], hsum[2] must start at 0 for this batch:
        // (initialize before use below via barrier-ordered writes)
        __syncthreads();
        float h_j = hsum[0], h_f = hsum[1], h_w = hsum[2];
        __syncthreads();
        if (t == 0) { hsum[1] = 0.f; hsum[2] = 0.f; }
        __syncthreads();

        float mi = h_f + h_w - h_j;
        nmi_sum += 2.f * mi / (h_f + h_w + EPSF);
    }

    if (t == 0) {
        // restore min/max sentinels for the next call
        #pragma unroll
        for (int k = 0; k < 4; k++) {
            g_minmax[k * 2 + 0] = 0xFFFFFFFFu;
            g_minmax[k * 2 + 1] = 0u;
        }
        float mse = 0.f;
        #pragma unroll
        for (int i = 0; i < BATCH * 12; i++) {
            float d = pred[i] - tru[i];
            mse += d * d;
        }
        mse /= (float)(BATCH * 12);
        out[0] = mse - nmi_sum / (float)BATCH;
    }
}

extern "C" void kernel_launch(void* const* d_in, const int* in_sizes, int n_in,
                              void* d_out, int out_size) {
    const float* pred    = (const float*)d_in[0];
    const float* tru     = (const float*)d_in[1];
    const float* fixedp  = (const float*)d_in[2];
    const float* warpedp = (const float*)d_in[3];

    dim3 g1(444, BATCH);
    minmaxK<<<g1, 256>>>((const float4*)fixedp, (const float4*)warpedp);

    dim3 g2(296, BATCH);
    histK<<<g2, 256>>>(fixedp, warpedp);

    finalK<<<1, 256>>>(pred, tru, (float*)d_out);
}